// round 12
// baseline (speedup 1.0000x reference)
#include <cuda_runtime.h>
#include <math.h>

// x[B=32, C=1, F=128, T=4096] fp32 -> out[B, C, T, F] fp32 (PCEN).
#define NB 32
#define NF 128
#define NT 4096
#define EPSF 1e-5f
#define HALF 2048
#define NIT 8             // iterations per half: 8 x 256 t

__device__ __forceinline__ float flg2(float v) {
    float r; asm("lg2.approx.f32 %0, %1;" : "=f"(r) : "f"(v)); return r;
}
__device__ __forceinline__ float fex2(float v) {
    float r; asm("ex2.approx.f32 %0, %1;" : "=f"(r) : "f"(v)); return r;
}

// Block = 512 threads = 16 warps = 16 f-rows x ONE time-half (grid T-split).
// R8 structure (proven fastest) with ONE change: the block-wide
// __syncthreads is replaced by two independent 8-warp named-barrier groups
// (f 0-7 / f 8-15), each with its own half-tile — halving barrier width and
// decoupling the two groups' drift. Stores become 32B (8f) segments: full
// sectors, coalescing preserved.
__global__ __launch_bounds__(512, 3)
void pcen_kernel(const float* __restrict__ x,
                 const float* __restrict__ alpha,
                 const float* __restrict__ delta,
                 const float* __restrict__ rparam,
                 float* __restrict__ out)
{
    // [grp][buf][hh][t-octet][f(8) + pad] — conflict-free on both phases
    __shared__ float4 tile4[2][2][2][32][9];   // 36.9KB

    const int tid  = threadIdx.x;
    const int wid  = tid >> 5;
    const int lane = tid & 31;
    const int grp  = wid >> 3;                  // barrier/transpose group
    const int h    = blockIdx.x & 1;            // time half
    const int fgi  = (blockIdx.x >> 1) & 7;
    const int b    = blockIdx.x >> 4;
    const int fg   = fgi << 4;
    const int f    = fg + wid;

    // s from t_val = 256
    const double sD = (sqrt(1.0 + 4.0 * 65536.0) - 1.0) / (2.0 * 65536.0);
    const float s  = (float)sD;
    const float c  = 1.0f - s;
    const float c2 = c * c,  c3 = c2 * c,  c4 = c2 * c2;
    const float c5 = c4 * c, c6 = c4 * c2, c7 = c4 * c3, c8 = c4 * c4;

    const double lc = log((double)c);
    const float c8pow   = (float)exp(lc * 8.0 * (double)lane);    // c^(8*lane)
    const float c8inv   = (float)exp(-lc * 8.0 * (double)lane);   // c^(-8*lane)
    const float c8powm1 = (float)exp(lc * 8.0 * (double)(lane - 1));
    const float c8pow1  = c8pow * c8;                             // c^(8*(lane+1))

    // Per-f parameters (uniform per warp)
    const float na  = -expf(alpha[f]);
    const float d   = expf(delta[f]);
    const float rr  = expf(rparam[f]);
    const float drr = fex2(rr * flg2(d));

    const long row = ((long)(b * NF + f)) * NT;
    const float4* xr4 = (const float4*)(x + row);
    const float x0 = __ldg(&x[row]);

    // Carry in M-units (m = s*M).  M_{-1} = x0/s  =>  m_0 = x0 (to rounding).
    float carryM;
    if (h == 0) {
        carryM = x0 / s;
    } else {
        // pass A: exact M state at t=2047, scan-free & coalesced (x-units)
        const float cinv256 = (float)exp(-lc * 256.0);
        float A = 0.0f, w = 1.0f;
        #pragma unroll
        for (int i = 0; i < NIT; ++i) {
            float4 a0 = __ldg(&xr4[i * 64 + 2 * lane]);
            float4 a1 = __ldg(&xr4[i * 64 + 2 * lane + 1]);
            float L = a0.x;
            L = fmaf(c, L, a0.y); L = fmaf(c, L, a0.z);
            L = fmaf(c, L, a0.w); L = fmaf(c, L, a1.x);
            L = fmaf(c, L, a1.y); L = fmaf(c, L, a1.z);
            L = fmaf(c, L, a1.w);
            A = fmaf(L, w, A);
            w *= cinv256;
        }
        float v = A * c8inv;
        #pragma unroll
        for (int off = 16; off >= 1; off >>= 1)
            v += __shfl_xor_sync(0xffffffffu, v, off);
        carryM = fmaf((float)exp(lc * 2048.0), x0 / s,
                      v * (float)exp(lc * 2040.0));   // M_2047
    }

    const float4* xpre = xr4 + h * (HALF / 4) + 2 * lane;
    float4 xv0 = __ldg(&xpre[0]);
    float4 xv1 = __ldg(&xpre[1]);

    // read-phase mapping within the 256-thread group
    const int wl   = wid & 7;           // f within group (write phase)
    const int gt   = tid & 255;         // thread id within group
    const int fl   = gt & 7;            // f within group (read phase)
    const int tseg = gt >> 3;           // t-octet 0..31

    // loop-carried output pointer: (b, t = h*HALF + tseg*8, f = fg + grp*8 + fl)
    float* op = &out[((long)b * NT + (long)h * HALF + tseg * 8) * NF
                     + fg + grp * 8 + fl];

    int buf = 0;
    for (int it = 0; it < NIT; ++it, buf ^= 1) {
        // --- zero-carry L-chain in x-units (pure FFMA) ---
        float L0 = xv0.x;
        float L1 = fmaf(c, L0, xv0.y);
        float L2 = fmaf(c, L1, xv0.z);
        float L3 = fmaf(c, L2, xv0.w);
        float L4 = fmaf(c, L3, xv1.x);
        float L5 = fmaf(c, L4, xv1.y);
        float L6 = fmaf(c, L5, xv1.z);
        float L7 = fmaf(c, L6, xv1.w);

        // --- warp scan of rescaled segment totals ---
        float u0 = L7 * c8inv;
        float u  = u0;
        #pragma unroll
        for (int off = 1; off < 32; off <<= 1) {
            float n = __shfl_up_sync(0xffffffffu, u, off);
            if (lane >= off) u += n;
        }
        float uex = u - u0;                            // exact 0 on lane 0
        float B   = s * fmaf(c8powm1, uex, c8pow * carryM);  // s*MinM
        carryM = __shfl_sync(0xffffffffu,
                             fmaf(c8pow, u, c8pow1 * carryM), 31);

        // --- recombine (R8-exact):  e_k = c^{k+1}*B + s*L_k + eps ---
        float e0 = fmaf(c,  B, fmaf(s, L0, EPSF));
        float e1 = fmaf(c2, B, fmaf(s, L1, EPSF));
        float e2 = fmaf(c3, B, fmaf(s, L2, EPSF));
        float e3 = fmaf(c4, B, fmaf(s, L3, EPSF));

        float p0 = fex2(rr * flg2(fmaf(xv0.x, fex2(na * flg2(e0)), d))) - drr;
        float p1 = fex2(rr * flg2(fmaf(xv0.y, fex2(na * flg2(e1)), d))) - drr;
        float p2 = fex2(rr * flg2(fmaf(xv0.z, fex2(na * flg2(e2)), d))) - drr;
        float p3 = fex2(rr * flg2(fmaf(xv0.w, fex2(na * flg2(e3)), d))) - drr;
        tile4[grp][buf][0][lane][wl] = make_float4(p0, p1, p2, p3);

        float e4 = fmaf(c5, B, fmaf(s, L4, EPSF));
        float e5 = fmaf(c6, B, fmaf(s, L5, EPSF));
        float e6 = fmaf(c7, B, fmaf(s, L6, EPSF));
        float e7 = fmaf(c8, B, fmaf(s, L7, EPSF));

        p0 = fex2(rr * flg2(fmaf(xv1.x, fex2(na * flg2(e4)), d))) - drr;
        p1 = fex2(rr * flg2(fmaf(xv1.y, fex2(na * flg2(e5)), d))) - drr;
        p2 = fex2(rr * flg2(fmaf(xv1.z, fex2(na * flg2(e6)), d))) - drr;
        p3 = fex2(rr * flg2(fmaf(xv1.w, fex2(na * flg2(e7)), d))) - drr;
        tile4[grp][buf][1][lane][wl] = make_float4(p0, p1, p2, p3);

        // branch-free prefetch (wraps to chunk 0 on last iter)
        int nb = ((it + 1) & 7) << 6;
        xv0 = __ldg(&xpre[nb]);
        xv1 = __ldg(&xpre[nb + 1]);

        // narrow named barrier: only this group's 256 threads
        asm volatile("bar.sync %0, 256;" :: "r"(grp + 1) : "memory");

        // read transposed (2x LDS.128, conflict-free), 8x coalesced STG.32
        float4 v0 = tile4[grp][buf][0][tseg][fl];
        float4 v1 = tile4[grp][buf][1][tseg][fl];
        op[0]      = v0.x;
        op[NF]     = v0.y;
        op[2 * NF] = v0.z;
        op[3 * NF] = v0.w;
        op[4 * NF] = v1.x;
        op[5 * NF] = v1.y;
        op[6 * NF] = v1.z;
        op[7 * NF] = v1.w;
        op += 256 * NF;
    }
}

extern "C" void kernel_launch(void* const* d_in, const int* in_sizes, int n_in,
                              void* d_out, int out_size) {
    (void)in_sizes; (void)n_in; (void)out_size;
    const float* x     = (const float*)d_in[0];
    const float* alpha = (const float*)d_in[1];
    const float* delta = (const float*)d_in[2];
    const float* rpar  = (const float*)d_in[3];
    float* out = (float*)d_out;

    // 512 blocks = 32 b x 8 f-groups(16) x 2 time-halves; 512 threads.
    pcen_kernel<<<NB * (NF / 16) * 2, 512>>>(x, alpha, delta, rpar, out);
}

// round 14
// speedup vs baseline: 1.0008x; 1.0008x over previous
#include <cuda_runtime.h>
#include <math.h>

// x[B=32, C=1, F=128, T=4096] fp32 -> out[B, C, T, F] fp32 (PCEN).
#define NB 32
#define NF 128
#define NT 4096
#define EPSF 1e-5f
#define HALF 2048
#define NIT 8             // iterations per half: 8 x 256 t

__device__ __forceinline__ float flg2(float v) {
    float r; asm("lg2.approx.f32 %0, %1;" : "=f"(r) : "f"(v)); return r;
}
__device__ __forceinline__ float fex2(float v) {
    float r; asm("ex2.approx.f32 %0, %1;" : "=f"(r) : "f"(v)); return r;
}

// Block = 256 threads = 8 warps = 8 f-rows x ONE time-half (grid T-split).
// Exact R8 per-warp pipeline (L-chain in x-units, 5-shfl rescaled scan,
// parallel c^1..c^8 recombine with eps folded, float4 transpose tile,
// prefetch-before-barrier).  Re-blocked for occupancy: 6 blocks/SM = 48
// warps (75%) and a finer-grained wave structure (1024 half-size blocks).
__global__ __launch_bounds__(256, 6)
void pcen_kernel(const float* __restrict__ x,
                 const float* __restrict__ alpha,
                 const float* __restrict__ delta,
                 const float* __restrict__ rparam,
                 float* __restrict__ out)
{
    __shared__ float4 tile4[2][2][32][9];   // [buf][hh][t-octet][f(8)+pad] 18.4KB

    const int tid  = threadIdx.x;
    const int wid  = tid >> 5;
    const int lane = tid & 31;
    const int h    = blockIdx.x & 1;            // time half
    const int fgi  = (blockIdx.x >> 1) & 15;
    const int b    = blockIdx.x >> 5;
    const int fg   = fgi << 3;
    const int f    = fg + wid;

    // s from t_val = 256
    const double sD = (sqrt(1.0 + 4.0 * 65536.0) - 1.0) / (2.0 * 65536.0);
    const float s  = (float)sD;
    const float c  = 1.0f - s;
    const float c2 = c * c,  c3 = c2 * c,  c4 = c2 * c2;
    const float c5 = c4 * c, c6 = c4 * c2, c7 = c4 * c3, c8 = c4 * c4;

    const double lc = log((double)c);
    const float c8pow   = (float)exp(lc * 8.0 * (double)lane);    // c^(8*lane)
    const float c8inv   = (float)exp(-lc * 8.0 * (double)lane);   // c^(-8*lane)
    const float c8powm1 = (float)exp(lc * 8.0 * (double)(lane - 1));
    const float c8pow1  = c8pow * c8;                             // c^(8*(lane+1))

    // Per-f parameters (uniform per warp)
    const float na  = -expf(alpha[f]);
    const float d   = expf(delta[f]);
    const float rr  = expf(rparam[f]);
    const float drr = fex2(rr * flg2(d));

    const long row = ((long)(b * NF + f)) * NT;
    const float4* xr4 = (const float4*)(x + row);
    const float x0 = __ldg(&x[row]);

    // Carry in M-units (m = s*M).  M_{-1} = x0/s  =>  m_0 = x0 (to rounding).
    float carryM;
    if (h == 0) {
        carryM = x0 / s;
    } else {
        // pass A: exact M state at t=2047, scan-free & coalesced (x-units)
        const float cinv256 = (float)exp(-lc * 256.0);
        float A = 0.0f, w = 1.0f;
        #pragma unroll
        for (int i = 0; i < NIT; ++i) {
            float4 a0 = __ldg(&xr4[i * 64 + 2 * lane]);
            float4 a1 = __ldg(&xr4[i * 64 + 2 * lane + 1]);
            float L = a0.x;
            L = fmaf(c, L, a0.y); L = fmaf(c, L, a0.z);
            L = fmaf(c, L, a0.w); L = fmaf(c, L, a1.x);
            L = fmaf(c, L, a1.y); L = fmaf(c, L, a1.z);
            L = fmaf(c, L, a1.w);
            A = fmaf(L, w, A);
            w *= cinv256;
        }
        float v = A * c8inv;
        #pragma unroll
        for (int off = 16; off >= 1; off >>= 1)
            v += __shfl_xor_sync(0xffffffffu, v, off);
        carryM = fmaf((float)exp(lc * 2048.0), x0 / s,
                      v * (float)exp(lc * 2040.0));   // M_2047
    }

    const float4* xpre = xr4 + h * (HALF / 4) + 2 * lane;
    float4 xv0 = __ldg(&xpre[0]);
    float4 xv1 = __ldg(&xpre[1]);

    const int fl   = tid & 7;           // read-phase f
    const int tseg = tid >> 3;          // read-phase t-octet 0..31

    // loop-carried output pointer: (b, t = h*HALF + tseg*8, f = fg+fl)
    float* op = &out[((long)b * NT + (long)h * HALF + tseg * 8) * NF + fg + fl];

    int buf = 0;
    for (int it = 0; it < NIT; ++it, buf ^= 1) {
        // --- zero-carry L-chain in x-units (pure FFMA) ---
        float L0 = xv0.x;
        float L1 = fmaf(c, L0, xv0.y);
        float L2 = fmaf(c, L1, xv0.z);
        float L3 = fmaf(c, L2, xv0.w);
        float L4 = fmaf(c, L3, xv1.x);
        float L5 = fmaf(c, L4, xv1.y);
        float L6 = fmaf(c, L5, xv1.z);
        float L7 = fmaf(c, L6, xv1.w);

        // --- warp scan of rescaled segment totals ---
        float u0 = L7 * c8inv;
        float u  = u0;
        #pragma unroll
        for (int off = 1; off < 32; off <<= 1) {
            float n = __shfl_up_sync(0xffffffffu, u, off);
            if (lane >= off) u += n;
        }
        float uex = u - u0;                            // exact 0 on lane 0
        float B   = s * fmaf(c8powm1, uex, c8pow * carryM);  // s*MinM
        carryM = __shfl_sync(0xffffffffu,
                             fmaf(c8pow, u, c8pow1 * carryM), 31);

        // --- recombine (R8-exact):  e_k = c^{k+1}*B + s*L_k + eps ---
        float e0 = fmaf(c,  B, fmaf(s, L0, EPSF));
        float e1 = fmaf(c2, B, fmaf(s, L1, EPSF));
        float e2 = fmaf(c3, B, fmaf(s, L2, EPSF));
        float e3 = fmaf(c4, B, fmaf(s, L3, EPSF));

        float p0 = fex2(rr * flg2(fmaf(xv0.x, fex2(na * flg2(e0)), d))) - drr;
        float p1 = fex2(rr * flg2(fmaf(xv0.y, fex2(na * flg2(e1)), d))) - drr;
        float p2 = fex2(rr * flg2(fmaf(xv0.z, fex2(na * flg2(e2)), d))) - drr;
        float p3 = fex2(rr * flg2(fmaf(xv0.w, fex2(na * flg2(e3)), d))) - drr;
        tile4[buf][0][lane][wid] = make_float4(p0, p1, p2, p3);

        float e4 = fmaf(c5, B, fmaf(s, L4, EPSF));
        float e5 = fmaf(c6, B, fmaf(s, L5, EPSF));
        float e6 = fmaf(c7, B, fmaf(s, L6, EPSF));
        float e7 = fmaf(c8, B, fmaf(s, L7, EPSF));

        p0 = fex2(rr * flg2(fmaf(xv1.x, fex2(na * flg2(e4)), d))) - drr;
        p1 = fex2(rr * flg2(fmaf(xv1.y, fex2(na * flg2(e5)), d))) - drr;
        p2 = fex2(rr * flg2(fmaf(xv1.z, fex2(na * flg2(e6)), d))) - drr;
        p3 = fex2(rr * flg2(fmaf(xv1.w, fex2(na * flg2(e7)), d))) - drr;
        tile4[buf][1][lane][wid] = make_float4(p0, p1, p2, p3);

        // branch-free prefetch (wraps to chunk 0 on last iter)
        int nb = ((it + 1) & 7) << 6;
        xv0 = __ldg(&xpre[nb]);
        xv1 = __ldg(&xpre[nb + 1]);

        __syncthreads();

        // read transposed (2x LDS.128, conflict-free), 8x coalesced STG.32
        float4 v0 = tile4[buf][0][tseg][fl];
        float4 v1 = tile4[buf][1][tseg][fl];
        op[0]      = v0.x;
        op[NF]     = v0.y;
        op[2 * NF] = v0.z;
        op[3 * NF] = v0.w;
        op[4 * NF] = v1.x;
        op[5 * NF] = v1.y;
        op[6 * NF] = v1.z;
        op[7 * NF] = v1.w;
        op += 256 * NF;
    }
}

extern "C" void kernel_launch(void* const* d_in, const int* in_sizes, int n_in,
                              void* d_out, int out_size) {
    (void)in_sizes; (void)n_in; (void)out_size;
    const float* x     = (const float*)d_in[0];
    const float* alpha = (const float*)d_in[1];
    const float* delta = (const float*)d_in[2];
    const float* rpar  = (const float*)d_in[3];
    float* out = (float*)d_out;

    // 1024 blocks = 32 b x 16 f-groups(8) x 2 time-halves; 256 threads.
    pcen_kernel<<<NB * (NF / 8) * 2, 256>>>(x, alpha, delta, rpar, out);
}

// round 17
// speedup vs baseline: 1.0364x; 1.0356x over previous
#include <cuda_runtime.h>
#include <math.h>

// x[B=32, C=1, F=128, T=4096] fp32 -> out[B, C, T, F] fp32 (PCEN).
#define NB 32
#define NF 128
#define NT 4096
#define EPSF 1e-5f
#define HALF 2048
#define NIT 8             // iterations per half: 8 x 256 t

__device__ __forceinline__ float flg2(float v) {
    float r; asm("lg2.approx.f32 %0, %1;" : "=f"(r) : "f"(v)); return r;
}
__device__ __forceinline__ float fex2(float v) {
    float r; asm("ex2.approx.f32 %0, %1;" : "=f"(r) : "f"(v)); return r;
}

// Block = 512 threads = 16 warps = 16 f-rows x ONE time-half (grid T-split).
// R8 pipeline with an instruction/register diet:
//  - midpoint-CORRECT recombine: second 4-element group restarts its
//    zero-carry chain (M'), carried from B4 = e3 - EPS (exact); reuses
//    c^1..c^4, eliminating c^5..c^8 from the live set. (+1 FFMA)
//  - parity-split transpose tile: even/odd f in separate half-planes so the
//    read phase emits 4x STG.64 (64B/quarter-warp) instead of 8x STG.32.
// R15 bug fixed: output pointer advance is 256 t per iteration (was 128 t).
__global__ __launch_bounds__(512, 3)
void pcen_kernel(const float* __restrict__ x,
                 const float* __restrict__ alpha,
                 const float* __restrict__ delta,
                 const float* __restrict__ rparam,
                 float* __restrict__ out)
{
    // [buf][hh][parity][lane][wid>>1]  (36.9KB)
    __shared__ float4 tile4[2][2][2][32][9];

    const int tid  = threadIdx.x;
    const int wid  = tid >> 5;
    const int lane = tid & 31;
    const int h    = blockIdx.x & 1;            // time half
    const int fgi  = (blockIdx.x >> 1) & 7;
    const int b    = blockIdx.x >> 4;
    const int fg   = fgi << 4;
    const int f    = fg + wid;

    // s from t_val = 256
    const double sD = (sqrt(1.0 + 4.0 * 65536.0) - 1.0) / (2.0 * 65536.0);
    const float s  = (float)sD;
    const float c  = 1.0f - s;
    const float c2 = c * c, c3 = c2 * c, c4 = c2 * c2;
    const float c8 = c4 * c4;

    const double lc = log((double)c);
    const float c8pow = (float)exp(lc * 8.0 * (double)lane);    // c^(8*lane)
    const float c8inv = (float)exp(-lc * 8.0 * (double)lane);   // c^(-8*lane)
    const float cinv8 = (float)exp(-lc * 8.0);                  // c^-8 (uniform)

    // Per-f parameters (uniform per warp)
    const float na  = -expf(alpha[f]);
    const float d   = expf(delta[f]);
    const float rr  = expf(rparam[f]);
    const float drr = fex2(rr * flg2(d));

    const long row = ((long)(b * NF + f)) * NT;
    const float4* xr4 = (const float4*)(x + row);
    const float x0 = __ldg(&x[row]);

    // Carry in M-units (m = s*M).  M_{-1} = x0/s  =>  m_0 = x0 (to rounding).
    float carryM;
    if (h == 0) {
        carryM = x0 / s;
    } else {
        // pass A: exact M state at t=2047, scan-free & coalesced (x-units)
        const float cinv256 = (float)exp(-lc * 256.0);
        float A = 0.0f, w = 1.0f;
        #pragma unroll
        for (int i = 0; i < NIT; ++i) {
            float4 a0 = __ldg(&xr4[i * 64 + 2 * lane]);
            float4 a1 = __ldg(&xr4[i * 64 + 2 * lane + 1]);
            float L = a0.x;
            L = fmaf(c, L, a0.y); L = fmaf(c, L, a0.z);
            L = fmaf(c, L, a0.w); L = fmaf(c, L, a1.x);
            L = fmaf(c, L, a1.y); L = fmaf(c, L, a1.z);
            L = fmaf(c, L, a1.w);
            A = fmaf(L, w, A);
            w *= cinv256;
        }
        float v = A * c8inv;
        #pragma unroll
        for (int off = 16; off >= 1; off >>= 1)
            v += __shfl_xor_sync(0xffffffffu, v, off);
        carryM = fmaf((float)exp(lc * 2048.0), x0 / s,
                      v * (float)exp(lc * 2040.0));   // M_2047
    }

    const float4* xpre = xr4 + h * (HALF / 4) + 2 * lane;
    float4 xv0 = __ldg(&xpre[0]);
    float4 xv1 = __ldg(&xpre[1]);

    // read-phase mapping: fp = f-pair, tq = t-quad
    const int fp = tid & 7;
    const int tq = tid >> 3;            // 0..63
    const int rhh = tq & 1;
    const int rln = tq >> 1;

    // write-phase tile coords
    const int par = wid & 1;
    const int col = wid >> 1;

    // loop-carried output pointer: (b, t = h*HALF + tq*4, f = fg + 2*fp)
    float2* op2 = (float2*)(out + ((long)b * NT + (long)h * HALF + tq * 4) * NF
                            + fg + 2 * fp);

    int buf = 0;
    for (int it = 0; it < NIT; ++it, buf ^= 1) {
        // --- zero-carry chains in x-units (midpoint-correct split) ---
        float L0 = xv0.x;
        float L1 = fmaf(c, L0, xv0.y);
        float L2 = fmaf(c, L1, xv0.z);
        float L3 = fmaf(c, L2, xv0.w);
        float M4 = xv1.x;                       // restarted chain M'
        float M5 = fmaf(c, M4, xv1.y);
        float M6 = fmaf(c, M5, xv1.z);
        float M7 = fmaf(c, M6, xv1.w);
        float L7 = fmaf(c4, L3, M7);            // full segment end for scan

        // --- warp scan of rescaled segment totals ---
        float u0 = L7 * c8inv;
        float u  = u0;
        #pragma unroll
        for (int off = 1; off < 32; off <<= 1) {
            float n = __shfl_up_sync(0xffffffffu, u, off);
            if (lane >= off) u += n;
        }
        float uex = u - u0;                            // exact 0 on lane 0
        float B   = s * (c8pow * fmaf(cinv8, uex, carryM));  // s*MinM
        carryM = __shfl_sync(0xffffffffu,
                             c8pow * fmaf(c8, carryM, u), 31);

        // --- recombine group A:  e_k = c^{k+1}*B + s*L_k + eps ---
        float e0 = fmaf(c,  B, fmaf(s, L0, EPSF));
        float e1 = fmaf(c2, B, fmaf(s, L1, EPSF));
        float e2 = fmaf(c3, B, fmaf(s, L2, EPSF));
        float e3 = fmaf(c4, B, fmaf(s, L3, EPSF));

        float p0 = fex2(rr * flg2(fmaf(xv0.x, fex2(na * flg2(e0)), d))) - drr;
        float p1 = fex2(rr * flg2(fmaf(xv0.y, fex2(na * flg2(e1)), d))) - drr;
        float p2 = fex2(rr * flg2(fmaf(xv0.z, fex2(na * flg2(e2)), d))) - drr;
        float p3 = fex2(rr * flg2(fmaf(xv0.w, fex2(na * flg2(e3)), d))) - drr;
        tile4[buf][0][par][lane][col] = make_float4(p0, p1, p2, p3);

        // --- group B restarts from midpoint: B4 = s*M_3 = e3 - EPS (exact)
        float B4 = e3 - EPSF;
        float e4 = fmaf(c,  B4, fmaf(s, M4, EPSF));
        float e5 = fmaf(c2, B4, fmaf(s, M5, EPSF));
        float e6 = fmaf(c3, B4, fmaf(s, M6, EPSF));
        float e7 = fmaf(c4, B4, fmaf(s, M7, EPSF));

        p0 = fex2(rr * flg2(fmaf(xv1.x, fex2(na * flg2(e4)), d))) - drr;
        p1 = fex2(rr * flg2(fmaf(xv1.y, fex2(na * flg2(e5)), d))) - drr;
        p2 = fex2(rr * flg2(fmaf(xv1.z, fex2(na * flg2(e6)), d))) - drr;
        p3 = fex2(rr * flg2(fmaf(xv1.w, fex2(na * flg2(e7)), d))) - drr;
        tile4[buf][1][par][lane][col] = make_float4(p0, p1, p2, p3);

        // branch-free prefetch (wraps to chunk 0 on last iter)
        int nb = ((it + 1) & 7) << 6;
        xv0 = __ldg(&xpre[nb]);
        xv1 = __ldg(&xpre[nb + 1]);

        __syncthreads();

        // read transposed: f-pair (even,odd) planes, 2x LDS.128 conflict-free,
        // then 4x STG.64 (64B contiguous per quarter-warp)
        float4 v0 = tile4[buf][rhh][0][rln][fp];   // f = fg + 2*fp
        float4 v1 = tile4[buf][rhh][1][rln][fp];   // f = fg + 2*fp + 1
        op2[0]            = make_float2(v0.x, v1.x);
        op2[NF / 2]       = make_float2(v0.y, v1.y);
        op2[2 * (NF / 2)] = make_float2(v0.z, v1.z);
        op2[3 * (NF / 2)] = make_float2(v0.w, v1.w);
        op2 += 256 * NF / 2;    // advance 256 t (FIX: was 128 t)
    }
}

extern "C" void kernel_launch(void* const* d_in, const int* in_sizes, int n_in,
                              void* d_out, int out_size) {
    (void)in_sizes; (void)n_in; (void)out_size;
    const float* x     = (const float*)d_in[0];
    const float* alpha = (const float*)d_in[1];
    const float* delta = (const float*)d_in[2];
    const float* rpar  = (const float*)d_in[3];
    float* out = (float*)d_out;

    // 512 blocks = 32 b x 8 f-groups(16) x 2 time-halves; 512 threads.
    pcen_kernel<<<NB * (NF / 16) * 2, 512>>>(x, alpha, delta, rpar, out);
}